// round 17
// baseline (speedup 1.0000x reference)
#include <cuda_runtime.h>
#include <cuda_fp16.h>
#include <math.h>
#include <stdint.h>

#define Sdim 196
#define Bdim 64
#define Ndim 512
#define Ddim 1024
#define Hdim 8
#define Mc 9                 // 1 + H
#define ROWS (Sdim*Bdim)     // 12544
#define LN_EPS 1e-5f

// ---------------- scratch (static device globals; no allocations) ----------------
__device__ float d_g[Bdim*Ddim];
__device__ float d_gp[4*Bdim*Ddim];
__device__ float d_common[Bdim*Mc*Ddim];
__device__ float d_Q[Bdim*Hdim*Ddim];
__device__ float d_QW[Bdim*Hdim*Ddim];
__device__ float d_M[Bdim*Hdim*Ndim];       // raw logits (softmax fused into wsum)
__device__ float d_Qd[Bdim*Mc*Ddim];
__device__ float d_Kd[Bdim*Mc*Ddim];
__device__ float d_diff[Bdim*Ddim];
__device__ float d_cvec[Bdim*Ddim];
__device__ float d_part[4718592];           // split-K partials
__device__ float d_hbuf[(size_t)ROWS*Ddim];

// ---- side streams + events, created at static-init time ----
namespace {
struct Aux {
    cudaStream_t s1 = nullptr;
    cudaEvent_t eFork = nullptr, eK6 = nullptr;
    Aux() {
        int lo = 0, hi = 0;
        cudaDeviceGetStreamPriorityRange(&lo, &hi);
        cudaStreamCreateWithPriority(&s1, cudaStreamNonBlocking, lo);  // K6: low prio
        cudaEventCreateWithFlags(&eFork, cudaEventDisableTiming);
        cudaEventCreateWithFlags(&eK6,   cudaEventDisableTiming);
    }
};
Aux g_aux;
}

// ---------------- fp16 helpers (K6) ----------------
__device__ __forceinline__ uint32_t f2h2(float a, float b) {
    __half2 h = __floats2half2_rn(a, b);
    return *reinterpret_cast<uint32_t*>(&h);
}
__device__ __forceinline__ void mma16(float* c, const uint32_t* a, const uint32_t* b) {
    asm volatile("mma.sync.aligned.m16n8k16.row.col.f32.f16.f16.f32 "
        "{%0,%1,%2,%3}, {%4,%5,%6,%7}, {%8,%9}, {%0,%1,%2,%3};"
        : "+f"(c[0]), "+f"(c[1]), "+f"(c[2]), "+f"(c[3])
        : "r"(a[0]), "r"(a[1]), "r"(a[2]), "r"(a[3]), "r"(b[0]), "r"(b[1]));
}

// ------------- mean phase 1: partial sums over 49 timesteps per s-chunk ----------
__global__ __launch_bounds__(256) void mean_part(const float* __restrict__ in) {
    int idx = blockIdx.x * 256 + threadIdx.x;
    int sc = blockIdx.y;
    const float4* p = (const float4*)in + (size_t)sc * 49 * (Bdim*Ddim/4) + idx;
    float4 a0 = make_float4(0,0,0,0), a1 = a0, a2 = a0, a3 = a0;
    #pragma unroll 1
    for (int t = 0; t < 48; t += 4) {
        float4 v0 = p[(size_t)(t+0) * (Bdim*Ddim/4)];
        float4 v1 = p[(size_t)(t+1) * (Bdim*Ddim/4)];
        float4 v2 = p[(size_t)(t+2) * (Bdim*Ddim/4)];
        float4 v3 = p[(size_t)(t+3) * (Bdim*Ddim/4)];
        a0.x += v0.x; a0.y += v0.y; a0.z += v0.z; a0.w += v0.w;
        a1.x += v1.x; a1.y += v1.y; a1.z += v1.z; a1.w += v1.w;
        a2.x += v2.x; a2.y += v2.y; a2.z += v2.z; a2.w += v2.w;
        a3.x += v3.x; a3.y += v3.y; a3.z += v3.z; a3.w += v3.w;
    }
    float4 vl = p[(size_t)48 * (Bdim*Ddim/4)];
    float4 s;
    s.x = a0.x + a1.x + a2.x + a3.x + vl.x;
    s.y = a0.y + a1.y + a2.y + a3.y + vl.y;
    s.z = a0.z + a1.z + a2.z + a3.z + vl.z;
    s.w = a0.w + a1.w + a2.w + a3.w + vl.w;
    ((float4*)d_gp)[(size_t)sc * (Bdim*Ddim/4) + idx] = s;
}

__global__ __launch_bounds__(256) void mean_red() {
    int idx = blockIdx.x * 256 + threadIdx.x;
    const float4* p = (const float4*)d_gp;
    float4 p0 = p[idx], p1 = p[(Bdim*Ddim/4) + idx];
    float4 p2 = p[2*(Bdim*Ddim/4) + idx], p3 = p[3*(Bdim*Ddim/4) + idx];
    float4 g;
    g.x = (p0.x+p1.x+p2.x+p3.x) * (1.0f/Sdim);
    g.y = (p0.y+p1.y+p2.y+p3.y) * (1.0f/Sdim);
    g.z = (p0.z+p1.z+p2.z+p3.z) * (1.0f/Sdim);
    g.w = (p0.w+p1.w+p2.w+p3.w) * (1.0f/Sdim);
    ((float4*)d_g)[idx] = g;
    int b = idx >> 8, d4 = idx & 255;
    ((float4*)(d_common + (size_t)b * Mc * Ddim))[d4] = g;
}

// =================================================================================
// K6 persistent fp16 GEMM (unchanged from R16): 2-stage smem (34 KB), regs<=128.
// BM=128 BN=128 BK=32, warp tile 32x64. Grid=148, 784 tiles. At the mma.sync
// issue-rate floor (~0.25 instr/cyc/SM); chain must avoid the tensor pipe.
// =================================================================================
#define K6_TILES 784
#define K6_GRID 148
#define K6_SMEM (2*(16*(128+8) + 16*(128+8))*4)
__global__ __launch_bounds__(256, 2) void k6_gemm(
    const float* __restrict__ A, const float* __restrict__ Bmat, float* __restrict__ C)
{
    constexpr int BM = 128, BN = 128;
    constexpr int MI = 2, NI = 8;
    constexpr int LDA = BM + 8;
    constexpr int AW  = 16 * LDA;
    constexpr int LDB = BN + 8;
    constexpr int BW  = 16 * LDB;

    extern __shared__ uint32_t smem_[];
    uint32_t* As = smem_;
    uint32_t* Bs = smem_ + 2 * AW;

    const int tid  = threadIdx.x;
    const int warp = tid >> 5, lane = tid & 31;
    const int g = lane >> 2, t = lane & 3;
    const int wm = (warp >> 1) * 32;
    const int wn = (warp & 1) * 64;
    const int am  = tid & 127;
    const int aks = (tid >> 7) * 8;
    const int bkp = tid >> 4;
    const int bnn = (tid & 15) * 8;

    #pragma unroll 1
    for (int tile = blockIdx.x; tile < K6_TILES; tile += K6_GRID) {
        const int m0 = (tile >> 3) * BM, n0 = (tile & 7) * BN;
        const float* aptr = A + (size_t)(m0 + am) * Ddim + 2 * aks;
        const float* bptr = Bmat + n0 + bnn;

        float acc[MI][NI][4];
        #pragma unroll
        for (int i = 0; i < MI; i++)
            #pragma unroll
            for (int j = 0; j < NI; j++)
                #pragma unroll
                for (int q = 0; q < 4; q++) acc[i][j][q] = 0.f;

        float4 ar[4];
        float4 br[4];

        auto ldgA = [&](int k0) {
            #pragma unroll
            for (int c = 0; c < 4; c++)
                ar[c] = *(const float4*)(aptr + k0 + c * 4);
        };
        auto stsA = [&](int st) {
            uint32_t* dst = As + st * AW + aks * LDA + am;
            #pragma unroll
            for (int c = 0; c < 4; c++) {
                dst[(2*c    ) * LDA] = f2h2(ar[c].x, ar[c].y);
                dst[(2*c + 1) * LDA] = f2h2(ar[c].z, ar[c].w);
            }
        };
        auto ldgB = [&](int k0) {
            const float* r0 = bptr + (size_t)(k0 + 2*bkp) * Ddim;
            const float* r1 = r0 + Ddim;
            br[0] = *(const float4*)r0;  br[1] = *(const float4*)(r0 + 4);
            br[2] = *(const float4*)r1;  br[3] = *(const float4*)(r1 + 4);
        };
        auto stsB = [&](int st) {
            uint32_t* dst = Bs + st * BW + bkp * LDB + bnn;
            uint4 u0 = make_uint4(f2h2(br[0].x, br[2].x), f2h2(br[0].y, br[2].y),
                                  f2h2(br[0].z, br[2].z), f2h2(br[0].w, br[2].w));
            uint4 u1 = make_uint4(f2h2(br[1].x, br[3].x), f2h2(br[1].y, br[3].y),
                                  f2h2(br[1].z, br[3].z), f2h2(br[1].w, br[3].w));
            *(uint4*)(dst)     = u0;
            *(uint4*)(dst + 4) = u1;
        };
        auto compute = [&](int st) {
            const uint32_t* Ab = As + st * AW;
            const uint32_t* Bb = Bs + st * BW;
            #pragma unroll
            for (int s = 0; s < 2; s++) {
                uint32_t af[MI][4], bf[NI][2];
                #pragma unroll
                for (int i = 0; i < MI; i++) {
                    int mb = wm + 16 * i;
                    af[i][0] = Ab[(s*8 + t    ) * LDA + mb + g];
                    af[i][1] = Ab[(s*8 + t    ) * LDA + mb + g + 8];
                    af[i][2] = Ab[(s*8 + t + 4) * LDA + mb + g];
                    af[i][3] = Ab[(s*8 + t + 4) * LDA + mb + g + 8];
                }
                #pragma unroll
                for (int j = 0; j < NI; j++) {
                    bf[j][0] = Bb[(s*8 + t    ) * LDB + wn + 8*j + g];
                    bf[j][1] = Bb[(s*8 + t + 4) * LDB + wn + 8*j + g];
                }
                #pragma unroll
                for (int i = 0; i < MI; i++)
                    #pragma unroll
                    for (int j = 0; j < NI; j++)
                        mma16(acc[i][j], af[i], bf[j]);
            }
        };

        ldgA(0);  ldgB(0);
        stsA(0);  stsB(0);
        ldgA(32); ldgB(32);
        __syncthreads();

        int st = 0, k0 = 0;
        while (true) {
            int ks = k0 + 32;
            if (ks < Ddim) {
                stsA(st ^ 1); stsB(st ^ 1);
                int kl = k0 + 64;
                if (kl < Ddim) { ldgA(kl); ldgB(kl); }
                compute(st);
                __syncthreads();
                st ^= 1; k0 = ks;
            } else {
                compute(st);
                break;
            }
        }

        #pragma unroll
        for (int i = 0; i < MI; i++) {
            int r0 = m0 + wm + i * 16 + g;
            #pragma unroll
            for (int j = 0; j < NI; j++) {
                int cc = n0 + wn + j * 8 + 2 * t;
                *(float2*)(C + (size_t)r0 * Ddim + cc)       = make_float2(acc[i][j][0], acc[i][j][1]);
                *(float2*)(C + (size_t)(r0 + 8) * Ddim + cc) = make_float2(acc[i][j][2], acc[i][j][3]);
            }
        }
        __syncthreads();
    }
}

// =================================================================================
// SIMT fp32 GEMM for chain (FMA pipe — no tensor contention with K6).
// BM=BN=64, BK=16, 256 thr, 4x4 micro-tile (16 acc regs), 2-stage smem (~17 KB).
// Split-K partials layout [zz][M][ldc]; DUALB: hz selects Bmat/Bmat2.
// =================================================================================
template<bool TRANSB, int SPLITK, bool DUALB>
__global__ __launch_bounds__(256) void simt_gemm(
    const float* __restrict__ A, int lda, size_t strideA,
    const float* __restrict__ Bmat, const float* __restrict__ Bmat2,
    int ldb, size_t strideB,
    float* __restrict__ C, int ldc,
    int M, int K)
{
    constexpr int LD = 68;                   // 64 + 4 pad (float4-aligned)
    __shared__ float As[2][16][LD];
    __shared__ float Bs[2][16][LD];

    const int zz = blockIdx.z;
    const int hz = zz / SPLITK, sz = zz % SPLITK;
    if (DUALB && hz == 1) Bmat = Bmat2;
    A    += (size_t)hz * strideA + (size_t)sz * K;
    Bmat += (DUALB ? 0 : (size_t)hz * strideB)
          + (TRANSB ? (size_t)sz * K : (size_t)sz * K * ldb);
    C    += (size_t)zz * (size_t)M * ldc;

    const int tid = threadIdx.x;
    const int m0 = blockIdx.y * 64, n0 = blockIdx.x * 64;

    // A producer: row am, k-span ak4..ak4+3
    const int am  = tid & 63;
    const int ak4 = (tid >> 6) * 4;
    const float* aptr = A + (size_t)(m0 + am) * lda + ak4;

    // B producer
    const int kr  = tid >> 4;                // NN: k row 0..15
    const int ncs = (tid & 15) * 4;          // NN: n chunk
    const int bn  = tid & 63;                // T:  n row
    const int bk4 = (tid >> 6) * 4;          // T:  k chunk
    const float* bptrN = Bmat + (size_t)kr * ldb + n0 + ncs;
    const float* bptrT = Bmat + (size_t)(n0 + bn) * ldb + bk4;

    float4 ar, br;
    auto ldg = [&](int k0) {
        ar = *(const float4*)(aptr + k0);
        if (TRANSB) br = *(const float4*)(bptrT + k0);
        else        br = *(const float4*)(bptrN + (size_t)k0 * ldb);
    };
    auto sts = [&](int st) {
        As[st][ak4+0][am] = ar.x; As[st][ak4+1][am] = ar.y;
        As[st][ak4+2][am] = ar.z; As[st][ak4+3][am] = ar.w;
        if (TRANSB) {
            Bs[st][bk4+0][bn] = br.x; Bs[st][bk4+1][bn] = br.y;
            Bs[st][bk4+2][bn] = br.z; Bs[st][bk4+3][bn] = br.w;
        } else {
            *(float4*)&Bs[st][kr][ncs] = br;
        }
    };

    float acc[4][4];
    #pragma unroll
    for (int i = 0; i < 4; i++)
        #pragma unroll
        for (int j = 0; j < 4; j++) acc[i][j] = 0.f;

    const int m4 = (tid >> 4) * 4, n4 = (tid & 15) * 4;

    auto compute = [&](int st) {
        #pragma unroll
        for (int k = 0; k < 16; k++) {
            float4 a = *(const float4*)&As[st][k][m4];
            float4 b = *(const float4*)&Bs[st][k][n4];
            acc[0][0] += a.x*b.x; acc[0][1] += a.x*b.y; acc[0][2] += a.x*b.z; acc[0][3] += a.x*b.w;
            acc[1][0] += a.y*b.x; acc[1][1] += a.y*b.y; acc[1][2] += a.y*b.z; acc[1][3] += a.y*b.w;
            acc[2][0] += a.z*b.x; acc[2][1] += a.z*b.y; acc[2][2] += a.z*b.z; acc[2][3] += a.z*b.w;
            acc[3][0] += a.w*b.x; acc[3][1] += a.w*b.y; acc[3][2] += a.w*b.z; acc[3][3] += a.w*b.w;
        }
    };

    ldg(0); sts(0);
    ldg(16);
    __syncthreads();

    int st = 0, k0 = 0;
    while (true) {
        int ks = k0 + 16;
        if (ks < K) {
            sts(st ^ 1);
            int kl = k0 + 32;
            if (kl < K) ldg(kl);
            compute(st);
            __syncthreads();
            st ^= 1; k0 = ks;
        } else {
            compute(st);
            break;
        }
    }

    #pragma unroll
    for (int i = 0; i < 4; i++) {
        float4 v = make_float4(acc[i][0], acc[i][1], acc[i][2], acc[i][3]);
        *(float4*)(C + (size_t)(m0 + m4 + i) * ldc + n0 + n4) = v;
    }
}

template<int SK, bool BIAS>
__global__ __launch_bounds__(256) void splitk_reduce(
    const float* __restrict__ part, float* __restrict__ C,
    int ldc, size_t strideC, const float* __restrict__ bias, size_t strideBias,
    int M, int N, int nz)
{
    int idx = blockIdx.x * 256 + threadIdx.x;
    int perz = M * N / 4;
    if (idx >= nz * perz) return;
    int z = idx / perz, rem = idx % perz;
    int r = rem / (N / 4), c4 = rem % (N / 4);
    const float4* p = (const float4*)part;
    float4 s = p[((size_t)z * SK) * perz + rem];
    #pragma unroll
    for (int q = 1; q < SK; q++) {
        float4 v = p[((size_t)z * SK + q) * perz + rem];
        s.x += v.x; s.y += v.y; s.z += v.z; s.w += v.w;
    }
    if (BIAS) {
        float4 b = *(const float4*)(bias + (size_t)z * strideBias + c4 * 4);
        s.x += b.x; s.y += b.y; s.z += b.z; s.w += b.w;
    }
    *(float4*)(C + (size_t)z * strideC + (size_t)r * ldc + c4 * 4) = s;
}

// paired reduce for Qd/Kd (separate outputs + biases)
__global__ __launch_bounds__(256) void qdkd_reduce(
    const float* __restrict__ bq, const float* __restrict__ bk)
{
    const int perz = Bdim * Mc * Ddim / 4;
    int idx = blockIdx.x * 256 + threadIdx.x;
    if (idx >= 2 * perz) return;
    int z = idx / perz, rem = idx % perz;
    int c4 = rem & 255;
    const float4* p = (const float4*)d_part;
    float4 s = p[((size_t)z * 4) * perz + rem];
    #pragma unroll
    for (int q = 1; q < 4; q++) {
        float4 v = p[((size_t)z * 4 + q) * perz + rem];
        s.x += v.x; s.y += v.y; s.z += v.z; s.w += v.w;
    }
    const float* bias = z ? bk : bq;
    float4 b = *(const float4*)(bias + c4 * 4);
    s.x += b.x; s.y += b.y; s.z += b.z; s.w += b.w;
    float* out = z ? d_Kd : d_Qd;
    *(float4*)(out + (size_t)rem * 4) = s;
}

// ---------------- logits: 4 n-rows per warp, all 8 heads -------------------------
__global__ __launch_bounds__(256) void logits_kernel(const float* __restrict__ gnf) {
    int b = blockIdx.y;
    int warp = threadIdx.x >> 5, lane = threadIdx.x & 31;
    int n0 = blockIdx.x * 32 + warp * 4;
    const float* qw = d_QW + (size_t)b * (Hdim * Ddim);
    const float* g0 = gnf + ((size_t)b * Ndim + n0) * Ddim;

    float acc[4][Hdim];
    #pragma unroll
    for (int r = 0; r < 4; r++)
        #pragma unroll
        for (int h = 0; h < Hdim; h++) acc[r][h] = 0.f;

    #pragma unroll 1
    for (int k0 = 0; k0 < Ddim; k0 += 128) {
        int kk = k0 + lane * 4;
        float4 v0 = *(const float4*)(g0 + kk);
        float4 v1 = *(const float4*)(g0 + Ddim + kk);
        float4 v2 = *(const float4*)(g0 + 2*Ddim + kk);
        float4 v3 = *(const float4*)(g0 + 3*Ddim + kk);
        #pragma unroll
        for (int h = 0; h < Hdim; h++) {
            float4 q = *(const float4*)(qw + (size_t)h * Ddim + kk);
            acc[0][h] += v0.x*q.x + v0.y*q.y + v0.z*q.z + v0.w*q.w;
            acc[1][h] += v1.x*q.x + v1.y*q.y + v1.z*q.z + v1.w*q.w;
            acc[2][h] += v2.x*q.x + v2.y*q.y + v2.z*q.z + v2.w*q.w;
            acc[3][h] += v3.x*q.x + v3.y*q.y + v3.z*q.z + v3.w*q.w;
        }
    }
    #pragma unroll
    for (int r = 0; r < 4; r++)
        #pragma unroll
        for (int h = 0; h < Hdim; h++) {
            float a = acc[r][h];
            #pragma unroll
            for (int off = 16; off; off >>= 1) a += __shfl_xor_sync(0xffffffffu, a, off);
            if (lane == 0)
                d_M[(size_t)b * (Hdim*Ndim) + h * Ndim + n0 + r] = a * (1.0f / 32.0f);
        }
}

// ------- wsum with fused softmax: P = softmax(logits); closest = P @ gnf ---------
__global__ __launch_bounds__(256) void wsum_kernel(const float* __restrict__ gnf) {
    __shared__ float sP[Hdim * Ndim];
    __shared__ float4 sR[4 * 64 * Hdim];
    int b = blockIdx.y;
    int tid = threadIdx.x;
    int lane = tid & 31, w8 = tid >> 5;
    int nq = tid >> 6, dq = tid & 63;
    int d0 = blockIdx.x * 256 + dq * 4;

    const float4* Mb = (const float4*)(d_M + (size_t)b * (Hdim*Ndim));
    for (int i = tid; i < Hdim * Ndim / 4; i += 256)
        ((float4*)sP)[i] = Mb[i];
    __syncthreads();

    {
        float* row = sP + w8 * Ndim;
        float vals[Ndim / 32];
        float mx = -INFINITY;
        #pragma unroll
        for (int i = 0; i < Ndim / 32; i++) {
            vals[i] = row[lane + 32 * i];
            mx = fmaxf(mx, vals[i]);
        }
        #pragma unroll
        for (int off = 16; off; off >>= 1) mx = fmaxf(mx, __shfl_xor_sync(0xffffffffu, mx, off));
        float sum = 0.f;
        #pragma unroll
        for (int i = 0; i < Ndim / 32; i++) { vals[i] = expf(vals[i] - mx); sum += vals[i]; }
        #pragma unroll
        for (int off = 16; off; off >>= 1) sum += __shfl_xor_sync(0xffffffffu, sum, off);
        float inv = 1.0f / sum;
        #pragma unroll
        for (int i = 0; i < Ndim / 32; i++) row[lane + 32 * i] = vals[i] * inv;
    }
    __syncthreads();

    float4 acc[Hdim];
    #pragma unroll
    for (int h = 0; h < Hdim; h++) acc[h] = make_float4(0.f, 0.f, 0.f, 0.f);

    const float* gb = gnf + ((size_t)b * Ndim + nq * 128) * Ddim + d0;
    const float* pp = sP + nq * 128;
    #pragma unroll 1
    for (int n = 0; n < 128; n += 4) {
        float4 v0 = *(const float4*)(gb + (size_t)(n + 0) * Ddim);
        float4 v1 = *(const float4*)(gb + (size_t)(n + 1) * Ddim);
        float4 v2 = *(const float4*)(gb + (size_t)(n + 2) * Ddim);
        float4 v3 = *(const float4*)(gb + (size_t)(n + 3) * Ddim);
        #pragma unroll
        for (int h = 0; h < Hdim; h++) {
            float p0 = pp[h * Ndim + n], p1 = pp[h * Ndim + n + 1];
            float p2 = pp[h * Ndim + n + 2], p3 = pp[h * Ndim + n + 3];
            acc[h].x += p0*v0.x + p1*v1.x + p2*v2.x + p3*v3.x;
            acc[h].y += p0*v0.y + p1*v1.y + p2*v2.y + p3*v3.y;
            acc[h].z += p0*v0.z + p1*v1.z + p2*v2.z + p3*v3.z;
            acc[h].w += p0*v0.w + p1*v1.w + p2*v2.w + p3*v3.w;
        }
    }
    #pragma unroll
    for (int h = 0; h < Hdim; h++)
        sR[(nq * 64 + dq) * Hdim + h] = acc[h];
    __syncthreads();

    for (int item = tid; item < 64 * Hdim; item += 256) {
        int rdq = item >> 3, h = item & 7;
        float4 s = sR[rdq * Hdim + h];
        #pragma unroll
        for (int q = 1; q < 4; q++) {
            float4 v = sR[(q * 64 + rdq) * Hdim + h];
            s.x += v.x; s.y += v.y; s.z += v.z; s.w += v.w;
        }
        *(float4*)(d_common + ((size_t)b * Mc + 1 + h) * Ddim + blockIdx.x * 256 + rdq * 4) = s;
    }
}

// ------- diff-attention: Md = Qd·Kd/32, softmax rows, column weights, diff -------
__launch_bounds__(256)
__global__ void diff_attn_kernel() {
    __shared__ float sMd[Mc*Mc];
    __shared__ float sw[Mc];
    int b = blockIdx.x;
    int tid = threadIdx.x;
    int warp = tid >> 5, lane = tid & 31;

    const float* Qb = d_Qd + (size_t)b * Mc * Ddim;
    const float* Kb = d_Kd + (size_t)b * Mc * Ddim;
    for (int p = warp; p < Mc*Mc; p += 8) {
        int m = p / Mc, n = p % Mc;
        float a = 0.f;
        for (int k = lane; k < Ddim; k += 32) a += Qb[m*Ddim + k] * Kb[n*Ddim + k];
        #pragma unroll
        for (int off = 16; off; off >>= 1) a += __shfl_xor_sync(0xffffffffu, a, off);
        if (lane == 0) sMd[p] = a * (1.0f / 32.0f);
    }
    __syncthreads();
    if (tid < Mc) {
        float mx = -INFINITY;
        for (int n = 0; n < Mc; n++) mx = fmaxf(mx, sMd[tid*Mc + n]);
        float s = 0.f;
        for (int n = 0; n < Mc; n++) { float e = expf(sMd[tid*Mc + n] - mx); sMd[tid*Mc + n] = e; s += e; }
        float inv = 1.0f / s;
        for (int n = 0; n < Mc; n++) sMd[tid*Mc + n] *= inv;
    }
    __syncthreads();
    if (tid < Mc) {
        float w = 0.f;
        for (int m = 0; m < Mc; m++) w += sMd[m*Mc + tid];
        sw[tid] = w * (1.0f / Mc);
    }
    __syncthreads();
    const float* cb = d_common + (size_t)b * Mc * Ddim;
    for (int d = tid; d < Ddim; d += 256) {
        float ci = 0.f;
        #pragma unroll
        for (int n = 0; n < Mc; n++) ci += sw[n] * cb[n*Ddim + d];
        d_diff[b*Ddim + d] = d_g[b*Ddim + d] - ci;
    }
}

// -------- fused epilogue: h = relu(raw + cvec[b]); LayerNorm(h) -> out -----------
__launch_bounds__(256)
__global__ void ln_kernel(const float* __restrict__ gamma,
                          const float* __restrict__ beta,
                          float* __restrict__ out) {
    __shared__ float red[16];
    int r = blockIdx.x;
    int bb = r & (Bdim - 1);
    int tid = threadIdx.x, lane = tid & 31, warp = tid >> 5;
    float4 v = *(const float4*)(d_hbuf + (size_t)r * Ddim + tid * 4);
    float4 c = *(const float4*)(d_cvec + (size_t)bb * Ddim + tid * 4);
    v.x = fmaxf(v.x + c.x, 0.f); v.y = fmaxf(v.y + c.y, 0.f);
    v.z = fmaxf(v.z + c.z, 0.f); v.w = fmaxf(v.w + c.w, 0.f);
    float s  = v.x + v.y + v.z + v.w;
    float sq = v.x*v.x + v.y*v.y + v.z*v.z + v.w*v.w;
    #pragma unroll
    for (int off = 16; off; off >>= 1) {
        s  += __shfl_xor_sync(0xffffffffu, s,  off);
        sq += __shfl_xor_sync(0xffffffffu, sq, off);
    }
    if (lane == 0) { red[warp] = s; red[8 + warp] = sq; }
    __syncthreads();
    if (tid == 0) {
        float ts = 0.f, tq = 0.f;
        #pragma unroll
        for (int w = 0; w < 8; w++) { ts += red[w]; tq += red[8 + w]; }
        red[0] = ts; red[8] = tq;
    }
    __syncthreads();
    float mu  = red[0] * (1.0f / Ddim);
    float var = red[8] * (1.0f / Ddim) - mu * mu;
    float rstd = rsqrtf(var + LN_EPS);
    float4 g4 = *(const float4*)(gamma + tid * 4);
    float4 b4 = *(const float4*)(beta  + tid * 4);
    float4 o;
    o.x = (v.x - mu) * rstd * g4.x + b4.x;
    o.y = (v.y - mu) * rstd * g4.y + b4.y;
    o.z = (v.z - mu) * rstd * g4.z + b4.z;
    o.w = (v.w - mu) * rstd * g4.w + b4.w;
    *(float4*)(out + (size_t)r * Ddim + tid * 4) = o;
}

// =================================================================================
extern "C" void kernel_launch(void* const* d_in, const int* in_sizes, int n_in,
                              void* d_out, int out_size) {
    const float* input_feats = (const float*)d_in[0];
    const float* gnf         = (const float*)d_in[1];
    const float* agg_Wq      = (const float*)d_in[2];
    const float* agg_bq      = (const float*)d_in[3];
    const float* agg_Wk      = (const float*)d_in[4];
    const float* diff_Wq     = (const float*)d_in[6];
    const float* diff_bq     = (const float*)d_in[7];
    const float* diff_Wk     = (const float*)d_in[8];
    const float* diff_bk     = (const float*)d_in[9];
    const float* upd_W       = (const float*)d_in[10];
    const float* upd_b       = (const float*)d_in[11];
    const float* ln_gamma    = (const float*)d_in[12];
    const float* ln_beta     = (const float*)d_in[13];
    float* out = (float*)d_out;

    float *p_g, *p_common, *p_Q, *p_QW, *p_diff, *p_cvec, *p_h, *p_part;
    cudaGetSymbolAddress((void**)&p_g,      d_g);
    cudaGetSymbolAddress((void**)&p_common, d_common);
    cudaGetSymbolAddress((void**)&p_Q,      d_Q);
    cudaGetSymbolAddress((void**)&p_QW,     d_QW);
    cudaGetSymbolAddress((void**)&p_diff,   d_diff);
    cudaGetSymbolAddress((void**)&p_cvec,   d_cvec);
    cudaGetSymbolAddress((void**)&p_h,      d_hbuf);
    cudaGetSymbolAddress((void**)&p_part,   d_part);

    cudaFuncSetAttribute(k6_gemm,
        cudaFuncAttributeMaxDynamicSharedMemorySize, K6_SMEM);

    cudaStream_t s0 = 0;
    cudaStream_t s1 = g_aux.s1;

    // fork: root s1 into the captured graph, then K6 first (slot 1 on every SM)
    cudaEventRecord(g_aux.eFork, s0);
    cudaStreamWaitEvent(s1, g_aux.eFork, 0);
    k6_gemm<<<K6_GRID, 256, K6_SMEM, s1>>>(input_feats, upd_W, p_h);
    cudaEventRecord(g_aux.eK6, s1);

    // ---- chain on s0: SIMT FFMA gemms (no tensor-pipe contention with K6) ----
    mean_part<<<dim3(64, 4), 256, 0, s0>>>(input_feats);
    mean_red<<<64, 256, 0, s0>>>();

    // Q gemm (split-K=4, batched over h)  (slot 4 -> profiled)
    simt_gemm<false,4,false><<<dim3(16,1,Hdim*4), 256, 0, s0>>>(
        p_g, Ddim, 0,
        agg_Wq, nullptr, Ddim, (size_t)Ddim*Ddim,
        p_part, Ddim,
        Bdim, Ddim/4);

    // Q reduce (+bias)
    splitk_reduce<4,true><<<(Hdim*Bdim*Ddim/4 + 255)/256, 256, 0, s0>>>(
        p_part, p_Q, Hdim*Ddim, (size_t)Ddim, agg_bq, (size_t)Ddim,
        Bdim, Ddim, Hdim);

    // QW gemm (TRANSB, split-K=4)
    simt_gemm<true,4,false><<<dim3(16,1,Hdim*4), 256, 0, s0>>>(
        p_Q, Hdim*Ddim, (size_t)Ddim,
        agg_Wk, nullptr, Ddim, (size_t)Ddim*Ddim,
        p_part, Ddim,
        Bdim, Ddim/4);

    // QW reduce
    splitk_reduce<4,false><<<(Hdim*Bdim*Ddim/4 + 255)/256, 256, 0, s0>>>(
        p_part, p_QW, Hdim*Ddim, (size_t)Ddim, (const float*)nullptr, 0,
        Bdim, Ddim, Hdim);

    // logits (raw, scaled)
    logits_kernel<<<dim3(Ndim/32, Bdim), 256, 0, s0>>>(gnf);

    // wsum with fused softmax -> common[:,1:9,:]
    wsum_kernel<<<dim3(Ddim/256, Bdim), 256, 0, s0>>>(gnf);

    // Qd+Kd fused dual-B gemm (split-K=4)
    simt_gemm<false,4,true><<<dim3(16,Bdim*Mc/64,8), 256, 0, s0>>>(
        p_common, Ddim, 0,
        diff_Wq, diff_Wk, Ddim, 0,
        p_part, Ddim,
        Bdim*Mc, Ddim/4);

    // paired reduce -> d_Qd, d_Kd (+biases)
    qdkd_reduce<<<(2*Bdim*Mc*Ddim/4 + 255)/256, 256, 0, s0>>>(diff_bq, diff_bk);

    // diff = g - common_info
    diff_attn_kernel<<<Bdim, 256, 0, s0>>>();

    // cvec gemm+reduce
    simt_gemm<false,4,false><<<dim3(16,1,4), 256, 0, s0>>>(
        p_diff, Ddim, 0,
        upd_W + (size_t)Ddim*Ddim, nullptr, Ddim, 0,
        p_part, Ddim,
        Bdim, Ddim/4);
    splitk_reduce<4,true><<<(Bdim*Ddim/4 + 255)/256, 256, 0, s0>>>(
        p_part, p_cvec, Ddim, 0, upd_b, 0, Bdim, Ddim, 1);

    // join + fused bias/relu/LN
    cudaStreamWaitEvent(s0, g_aux.eK6, 0);
    ln_kernel<<<ROWS, 256, 0, s0>>>(ln_gamma, ln_beta, out);
}